// round 8
// baseline (speedup 1.0000x reference)
#include <cuda_runtime.h>
#include <cuda_bf16.h>

#define BATCH 4096
#define NHID  512
#define BR    32
#define NBKT  1024   // bucket key = lab>>5 ; node2 = 33+bkt, node1 = 1+(bkt>>5)

#define L0_BLOCKS 512          // 4096/8 groups, S=8
#define L1_SLOTS  544          // >= 32 + 4096/8 worst-case level-1 groups (S=8)
#define L2_SLOTS  2048         // >= 1024 + 4096/4 worst-case level-2 groups (S=4)

__device__ int   d_start[NBKT + 1];
__device__ int   d_cur[NBKT];
__device__ int   d_perm[BATCH];
__device__ int   d_g1off[33];        // prefix of level-1 group counts per node
__device__ int   d_g2off[NBKT + 1];  // prefix of level-2 group counts per bucket
__device__ float d_p[2][BATCH];      // [0]=level-1 p, [1]=level-2 p

// ---------------- tables kernel: hist + scans + task tables (NO scatter) ----------------
__global__ __launch_bounds__(1024, 1)
void tables_kernel(const int* __restrict__ labels)
{
    __shared__ int hist[NBKT];
    __shared__ int wsum[32];
    __shared__ int l1cnt[32];

    const int t    = threadIdx.x;
    const int wid  = t >> 5;
    const int lane = t & 31;

    hist[t] = 0;
    __syncthreads();
    #pragma unroll
    for (int i = 0; i < 4; i++)
        atomicAdd(&hist[labels[t + i * 1024] >> 5], 1);
    __syncthreads();

    // exclusive scan of hist (warp scan + warp-sum scan)
    const int h = hist[t];
    int v = h;
    #pragma unroll
    for (int o = 1; o < 32; o <<= 1) {
        int u = __shfl_up_sync(0xffffffffu, v, o);
        if (lane >= o) v += u;
    }
    if (lane == 31) wsum[wid] = v;
    __syncthreads();
    if (wid == 0) {
        int w = wsum[lane];
        #pragma unroll
        for (int o = 1; o < 32; o <<= 1) {
            int u = __shfl_up_sync(0xffffffffu, w, o);
            if (lane >= o) w += u;
        }
        wsum[lane] = w;
    }
    __syncthreads();
    const int excl = v + (wid > 0 ? wsum[wid - 1] : 0) - h;
    d_start[t] = excl;
    d_cur[t]   = excl;
    if (t == 0) d_start[NBKT] = BATCH;
    __syncthreads();

    // level-2 group prefix: ceil(n_bkt/4)
    int g2 = (h + 3) >> 2;
    int v2 = g2;
    #pragma unroll
    for (int o = 1; o < 32; o <<= 1) {
        int u = __shfl_up_sync(0xffffffffu, v2, o);
        if (lane >= o) v2 += u;
    }
    if (lane == 31) wsum[wid] = v2;
    __syncthreads();
    if (wid == 0) {
        int w = wsum[lane];
        #pragma unroll
        for (int o = 1; o < 32; o <<= 1) {
            int u = __shfl_up_sync(0xffffffffu, w, o);
            if (lane >= o) w += u;
        }
        wsum[lane] = w;
    }
    __syncthreads();
    const int incl2 = v2 + (wid > 0 ? wsum[wid - 1] : 0);
    d_g2off[t] = incl2 - g2;
    if (t == 1023) d_g2off[NBKT] = incl2;

    // level-1 group prefix: node w owns buckets [32w, 32w+32)
    {
        int c = hist[wid * 32 + lane];
        #pragma unroll
        for (int o = 16; o; o >>= 1) c += __shfl_xor_sync(0xffffffffu, c, o);
        if (lane == 0) l1cnt[wid] = (c + 7) >> 3;
    }
    __syncthreads();
    if (t == 0) {
        int acc = 0;
        d_g1off[0] = 0;
        #pragma unroll
        for (int g = 0; g < 32; g++) { acc += l1cnt[g]; d_g1off[g + 1] = acc; }
    }
}

// ---------------- scatter kernel: 16 blocks spread the scattered STGs ----------------
__global__ __launch_bounds__(256)
void scatter_kernel(const int* __restrict__ labels)
{
    const int i = blockIdx.x * 256 + threadIdx.x;
    const int p = atomicAdd(&d_cur[labels[i] >> 5], 1);
    d_perm[p] = i;
}

// largest k with off[k] <= i
__device__ __forceinline__ int find_bucket(const int* __restrict__ off, int n, int i)
{
    int lo = 0, hi = n;
    while (lo + 1 < hi) {
        int mid = (lo + hi) >> 1;
        if (off[mid] <= i) lo = mid; else hi = mid;
    }
    return lo;
}

// ---------------- group task: SMAX samples x one node, 4-warp h-split ----------------
// FUSE_OUT=false: write p to pout[sid].  FUSE_OUT=true: prologue prefetches
// d_p[0][sid]*d_p[1][sid] (latency hidden behind the 128-h mainloop) and the
// epilogue writes pout[sid] = that * p (final fused product).
template<int SMAX, bool FUSE_OUT, int UNROLL>
__device__ __forceinline__ void process_group(
    const float* __restrict__ x, const int* __restrict__ labels,
    const float* __restrict__ W, float* __restrict__ pout,
    float4* __restrict__ xsv,        // [SMAX*128]
    float*  __restrict__ part,       // [4][SMAX][32]
    int* __restrict__ sid_sm, int* __restrict__ step_sm, float* __restrict__ p01_sm,
    int node, int shift, int base, int S, bool use_perm)
{
    const int tid  = threadIdx.x;
    const int warp = tid >> 5;
    const int lane = tid & 31;

    if (tid < S) {
        const int sb = use_perm ? d_perm[base + tid] : (base + tid);
        sid_sm[tid]  = sb;
        step_sm[tid] = (labels[sb] >> shift) & 31;
        if (FUSE_OUT) p01_sm[tid] = d_p[0][sb] * d_p[1][sb];
    }
    __syncthreads();

    // Stage x for the S valid samples (128 threads = 128 float4 per sample)
    #pragma unroll
    for (int s = 0; s < SMAX; s++) {
        if (s < S) {
            const float4* xg = reinterpret_cast<const float4*>(x + (size_t)sid_sm[s] * NHID);
            xsv[s * 128 + tid] = xg[tid];
        }
    }
    __syncthreads();

    const float* __restrict__ Wq =
        W + (size_t)node * (NHID * BR) + (warp * 128) * BR + lane;

    float acc[SMAX];
    #pragma unroll
    for (int s = 0; s < SMAX; s++) acc[s] = 0.f;

    #pragma unroll UNROLL
    for (int t = 0; t < 32; t++) {
        const float w0 = __ldg(Wq + (4 * t + 0) * BR);
        const float w1 = __ldg(Wq + (4 * t + 1) * BR);
        const float w2 = __ldg(Wq + (4 * t + 2) * BR);
        const float w3 = __ldg(Wq + (4 * t + 3) * BR);
        #pragma unroll
        for (int s = 0; s < SMAX; s++) {
            const float4 xq = xsv[s * 128 + warp * 32 + t];   // broadcast LDS.128
            acc[s] = fmaf(xq.x, w0, acc[s]);
            acc[s] = fmaf(xq.y, w1, acc[s]);
            acc[s] = fmaf(xq.z, w2, acc[s]);
            acc[s] = fmaf(xq.w, w3, acc[s]);
        }
    }

    #pragma unroll
    for (int s = 0; s < SMAX; s++)
        part[(warp * SMAX + s) * 32 + lane] = acc[s];
    __syncthreads();

    #pragma unroll
    for (int si = warp; si < SMAX; si += 4) {
        float logit = part[(0 * SMAX + si) * 32 + lane]
                    + part[(1 * SMAX + si) * 32 + lane]
                    + part[(2 * SMAX + si) * 32 + lane]
                    + part[(3 * SMAX + si) * 32 + lane];
        float m = logit;
        #pragma unroll
        for (int o = 16; o; o >>= 1) m = fmaxf(m, __shfl_xor_sync(0xffffffffu, m, o));
        const float e = __expf(logit - m);
        float ssum = e;
        #pragma unroll
        for (int o = 16; o; o >>= 1) ssum += __shfl_xor_sync(0xffffffffu, ssum, o);
        if (si < S) {
            const float es = __shfl_sync(0xffffffffu, e, step_sm[si]);
            if (lane == 0) {
                const float p = es / ssum;
                pout[sid_sm[si]] = FUSE_OUT ? p01_sm[si] * p : p;
            }
        }
    }
}

// ---------------- levels 1+2 kernel: one grid so DRAM-streaming level-2 blocks
// overlap compute-heavy, L2-cached level-1 blocks (the R5 mixing win) ----------------
__global__ __launch_bounds__(128)
void level12_kernel(const float* __restrict__ x,
                    const int* __restrict__ labels,
                    const float* __restrict__ W)
{
    __shared__ float4 xsv[8 * 128];        // 16 KB
    __shared__ float  part[4 * 8 * 32];    // 4 KB
    __shared__ int    sid_sm[8];
    __shared__ int    step_sm[8];

    const int blk = blockIdx.x;

    if (blk < L1_SLOTS) {
        const int i = blk;
        if (i >= d_g1off[32]) return;
        const int g    = find_bucket(d_g1off, 32, i);
        const int base = d_start[g * 32] + (i - d_g1off[g]) * 8;
        const int S    = min(8, d_start[g * 32 + 32] - base);
        process_group<8, false, 4>(x, labels, W, d_p[0], xsv, part, sid_sm, step_sm,
                                   nullptr, 1 + g, /*shift=*/5, base, S, true);
    } else {
        const int i = blk - L1_SLOTS;
        if (i >= d_g2off[NBKT]) return;
        const int k    = find_bucket(d_g2off, NBKT, i);
        const int base = d_start[k] + (i - d_g2off[k]) * 4;
        const int S    = min(4, d_start[k + 1] - base);
        process_group<4, false, 8>(x, labels, W, d_p[1], xsv, part, sid_sm, step_sm,
                                   nullptr, 33 + k, /*shift=*/0, base, S, true);
    }
}

// ---------------- level 0 kernel: node 0 (L2-resident W) + fused final product --------
__global__ __launch_bounds__(128)
void level0_kernel(const float* __restrict__ x,
                   const int* __restrict__ labels,
                   const float* __restrict__ W,
                   float* __restrict__ out)
{
    __shared__ float4 xsv[8 * 128];        // 16 KB
    __shared__ float  part[4 * 8 * 32];    // 4 KB
    __shared__ int    sid_sm[8];
    __shared__ int    step_sm[8];
    __shared__ float  p01_sm[8];

    process_group<8, true, 4>(x, labels, W, out, xsv, part, sid_sm, step_sm, p01_sm,
                              /*node=*/0, /*shift=*/10, blockIdx.x * 8, 8, false);
}

extern "C" void kernel_launch(void* const* d_in, const int* in_sizes, int n_in,
                              void* d_out, int out_size)
{
    const float* x      = (const float*)d_in[0];   // [4096, 512] f32
    const int*   labels = (const int*)d_in[1];     // [4096] i32
    const float* W      = (const float*)d_in[2];   // [1057, 512, 32] f32
    float*       out    = (float*)d_out;           // [4096] f32

    tables_kernel <<<1, 1024>>>(labels);
    scatter_kernel<<<16, 256>>>(labels);
    level12_kernel<<<L1_SLOTS + L2_SLOTS, 128>>>(x, labels, W);
    level0_kernel <<<L0_BLOCKS, 128>>>(x, labels, W, out);
}

// round 9
// speedup vs baseline: 1.7905x; 1.7905x over previous
#include <cuda_runtime.h>
#include <cuda_bf16.h>

#define BATCH 4096
#define NHID  512
#define BR    32
#define NBKT  1024   // bucket key = lab>>5 ; node2 = 33+bkt, node1 = 1+(bkt>>5)

#define L0_BLOCKS 512          // 4096/8 groups, S=8
#define L1_SLOTS  544          // >= 32 + 4096/8 worst-case level-1 groups (S=8)
#define L2_SLOTS  2048         // >= 1024 + 4096/4 worst-case level-2 groups (S=4)

__device__ int   d_start[NBKT + 1];
__device__ int   d_cur[NBKT];
__device__ int   d_perm[BATCH];
__device__ int   d_g1off[33];        // prefix of level-1 group counts per node
__device__ int   d_g2off[NBKT + 1];  // prefix of level-2 group counts per bucket
__device__ float d_p[3][BATCH];      // per-level probabilities

// ---------------- tables kernel: hist + scans + task tables (NO scatter) ----------------
__global__ __launch_bounds__(1024, 1)
void tables_kernel(const int* __restrict__ labels)
{
    __shared__ int hist[NBKT];
    __shared__ int wsum[32];
    __shared__ int l1cnt[32];

    const int t    = threadIdx.x;
    const int wid  = t >> 5;
    const int lane = t & 31;

    hist[t] = 0;
    __syncthreads();
    #pragma unroll
    for (int i = 0; i < 4; i++)
        atomicAdd(&hist[labels[t + i * 1024] >> 5], 1);
    __syncthreads();

    // exclusive scan of hist (warp scan + warp-sum scan)
    const int h = hist[t];
    int v = h;
    #pragma unroll
    for (int o = 1; o < 32; o <<= 1) {
        int u = __shfl_up_sync(0xffffffffu, v, o);
        if (lane >= o) v += u;
    }
    if (lane == 31) wsum[wid] = v;
    __syncthreads();
    if (wid == 0) {
        int w = wsum[lane];
        #pragma unroll
        for (int o = 1; o < 32; o <<= 1) {
            int u = __shfl_up_sync(0xffffffffu, w, o);
            if (lane >= o) w += u;
        }
        wsum[lane] = w;
    }
    __syncthreads();
    const int excl = v + (wid > 0 ? wsum[wid - 1] : 0) - h;
    d_start[t] = excl;
    d_cur[t]   = excl;
    if (t == 0) d_start[NBKT] = BATCH;
    __syncthreads();

    // level-2 group prefix: ceil(n_bkt/4)
    int g2 = (h + 3) >> 2;
    int v2 = g2;
    #pragma unroll
    for (int o = 1; o < 32; o <<= 1) {
        int u = __shfl_up_sync(0xffffffffu, v2, o);
        if (lane >= o) v2 += u;
    }
    if (lane == 31) wsum[wid] = v2;
    __syncthreads();
    if (wid == 0) {
        int w = wsum[lane];
        #pragma unroll
        for (int o = 1; o < 32; o <<= 1) {
            int u = __shfl_up_sync(0xffffffffu, w, o);
            if (lane >= o) w += u;
        }
        wsum[lane] = w;
    }
    __syncthreads();
    const int incl2 = v2 + (wid > 0 ? wsum[wid - 1] : 0);
    d_g2off[t] = incl2 - g2;
    if (t == 1023) d_g2off[NBKT] = incl2;

    // level-1 group prefix: node w owns buckets [32w, 32w+32)
    {
        int c = hist[wid * 32 + lane];
        #pragma unroll
        for (int o = 16; o; o >>= 1) c += __shfl_xor_sync(0xffffffffu, c, o);
        if (lane == 0) l1cnt[wid] = (c + 7) >> 3;
    }
    __syncthreads();
    if (t == 0) {
        int acc = 0;
        d_g1off[0] = 0;
        #pragma unroll
        for (int g = 0; g < 32; g++) { acc += l1cnt[g]; d_g1off[g + 1] = acc; }
    }
}

// ---------------- scatter kernel: 16 blocks spread the scattered STGs ----------------
__global__ __launch_bounds__(256)
void scatter_kernel(const int* __restrict__ labels)
{
    const int i = blockIdx.x * 256 + threadIdx.x;
    const int p = atomicAdd(&d_cur[labels[i] >> 5], 1);
    d_perm[p] = i;
}

// largest k with off[k] <= i
__device__ __forceinline__ int find_bucket(const int* __restrict__ off, int n, int i)
{
    int lo = 0, hi = n;
    while (lo + 1 < hi) {
        int mid = (lo + hi) >> 1;
        if (off[mid] <= i) lo = mid; else hi = mid;
    }
    return lo;
}

// ---- shared prologue: fetch sample ids/steps and stage x -------------------------
template<int SMAX>
__device__ __forceinline__ void stage_samples(
    const float* __restrict__ x, const int* __restrict__ labels,
    float4* __restrict__ xsv, int* __restrict__ sid_sm, int* __restrict__ step_sm,
    int shift, int base, int S, bool use_perm)
{
    const int tid = threadIdx.x;
    if (tid < S) {
        const int sb = use_perm ? d_perm[base + tid] : (base + tid);
        sid_sm[tid]  = sb;
        step_sm[tid] = (labels[sb] >> shift) & 31;
    }
    __syncthreads();
    #pragma unroll
    for (int s = 0; s < SMAX; s++) {
        if (s < S) {
            const float4* xg = reinterpret_cast<const float4*>(x + (size_t)sid_sm[s] * NHID);
            xsv[s * 128 + tid] = xg[tid];
        }
    }
    __syncthreads();
}

// ---------------- scalar-W group task (levels 0/1: L2-resident regime) ----------------
template<int SMAX>
__device__ __forceinline__ void process_group_scalar(
    const float* __restrict__ x, const int* __restrict__ labels,
    const float* __restrict__ W, float* __restrict__ pout,
    float4* __restrict__ xsv, float* __restrict__ part,
    int* __restrict__ sid_sm, int* __restrict__ step_sm,
    int node, int shift, int base, int S, bool use_perm)
{
    const int tid  = threadIdx.x;
    const int warp = tid >> 5;
    const int lane = tid & 31;

    stage_samples<SMAX>(x, labels, xsv, sid_sm, step_sm, shift, base, S, use_perm);

    const float* __restrict__ Wq =
        W + (size_t)node * (NHID * BR) + (warp * 128) * BR + lane;

    float acc[SMAX];
    #pragma unroll
    for (int s = 0; s < SMAX; s++) acc[s] = 0.f;

    #pragma unroll 4
    for (int t = 0; t < 32; t++) {
        const float w0 = __ldg(Wq + (4 * t + 0) * BR);
        const float w1 = __ldg(Wq + (4 * t + 1) * BR);
        const float w2 = __ldg(Wq + (4 * t + 2) * BR);
        const float w3 = __ldg(Wq + (4 * t + 3) * BR);
        #pragma unroll
        for (int s = 0; s < SMAX; s++) {
            const float4 xq = xsv[s * 128 + warp * 32 + t];   // broadcast LDS.128
            acc[s] = fmaf(xq.x, w0, acc[s]);
            acc[s] = fmaf(xq.y, w1, acc[s]);
            acc[s] = fmaf(xq.z, w2, acc[s]);
            acc[s] = fmaf(xq.w, w3, acc[s]);
        }
    }

    #pragma unroll
    for (int s = 0; s < SMAX; s++)
        part[(warp * SMAX + s) * 32 + lane] = acc[s];
    __syncthreads();

    #pragma unroll
    for (int si = warp; si < SMAX; si += 4) {
        float logit = part[(0 * SMAX + si) * 32 + lane]
                    + part[(1 * SMAX + si) * 32 + lane]
                    + part[(2 * SMAX + si) * 32 + lane]
                    + part[(3 * SMAX + si) * 32 + lane];
        float m = logit;
        #pragma unroll
        for (int o = 16; o; o >>= 1) m = fmaxf(m, __shfl_xor_sync(0xffffffffu, m, o));
        const float e = __expf(logit - m);
        float ssum = e;
        #pragma unroll
        for (int o = 16; o; o >>= 1) ssum += __shfl_xor_sync(0xffffffffu, ssum, o);
        if (si < S) {
            const float es = __shfl_sync(0xffffffffu, e, step_sm[si]);
            if (lane == 0) pout[sid_sm[si]] = es / ssum;
        }
    }
}

// ---------------- float4-W group task (level 2: DRAM-streaming regime) ----------------
// lane = (g = lane>>3 h-phase, ci = lane&7 column-quad). One LDG.128 covers 4
// columns of one W row -> 4x bytes-in-flight per instruction vs LDG.32, which is
// what the MLP-limited DRAM stream needs. S=4 accumulator quads in registers.
__device__ __forceinline__ void process_group_vec4(
    const float* __restrict__ x, const int* __restrict__ labels,
    const float* __restrict__ W, float* __restrict__ pout,
    float4* __restrict__ xsv, float* __restrict__ part,
    int* __restrict__ sid_sm, int* __restrict__ step_sm,
    int node, int base, int S)
{
    const int tid  = threadIdx.x;
    const int warp = tid >> 5;
    const int lane = tid & 31;
    const int g    = lane >> 3;
    const int ci   = lane & 7;

    stage_samples<4>(x, labels, xsv, sid_sm, step_sm, /*shift=*/0, base, S, true);
    const float* xsf = reinterpret_cast<const float*>(xsv);   // xsf[s*512 + h_local(0..511)]

    const float4* __restrict__ Wv =
        reinterpret_cast<const float4*>(W + (size_t)node * (NHID * BR))
        + (warp * 128) * 8 + ci;

    float4 acc[4];
    #pragma unroll
    for (int s = 0; s < 4; s++) acc[s] = make_float4(0.f, 0.f, 0.f, 0.f);

    #pragma unroll 8
    for (int t = 0; t < 32; t++) {
        const int h = 4 * t + g;                       // warp-local row
        const float4 w = __ldg(Wv + h * 8);
        #pragma unroll
        for (int s = 0; s < 4; s++) {
            const float xv = xsf[s * 512 + warp * 128 + h];    // broadcast in 8-lane group
            acc[s].x = fmaf(xv, w.x, acc[s].x);
            acc[s].y = fmaf(xv, w.y, acc[s].y);
            acc[s].z = fmaf(xv, w.z, acc[s].z);
            acc[s].w = fmaf(xv, w.w, acc[s].w);
        }
    }

    // fold the 4 h-phases (lanes l, l^8, l^16, l^24 share ci)
    #pragma unroll
    for (int o = 8; o <= 16; o <<= 1) {
        #pragma unroll
        for (int s = 0; s < 4; s++) {
            acc[s].x += __shfl_xor_sync(0xffffffffu, acc[s].x, o);
            acc[s].y += __shfl_xor_sync(0xffffffffu, acc[s].y, o);
            acc[s].z += __shfl_xor_sync(0xffffffffu, acc[s].z, o);
            acc[s].w += __shfl_xor_sync(0xffffffffu, acc[s].w, o);
        }
    }
    if (g == 0) {
        float4* part4 = reinterpret_cast<float4*>(part);
        #pragma unroll
        for (int s = 0; s < 4; s++)
            part4[(warp * 4 + s) * 8 + ci] = acc[s];           // conflict-free
    }
    __syncthreads();

    // epilogue: warp w finishes sample w; lane = column
    const int si = warp;
    float logit = part[(0 * 4 + si) * 32 + lane]
                + part[(1 * 4 + si) * 32 + lane]
                + part[(2 * 4 + si) * 32 + lane]
                + part[(3 * 4 + si) * 32 + lane];
    float m = logit;
    #pragma unroll
    for (int o = 16; o; o >>= 1) m = fmaxf(m, __shfl_xor_sync(0xffffffffu, m, o));
    const float e = __expf(logit - m);
    float ssum = e;
    #pragma unroll
    for (int o = 16; o; o >>= 1) ssum += __shfl_xor_sync(0xffffffffu, ssum, o);
    if (si < S) {
        const float es = __shfl_sync(0xffffffffu, e, step_sm[si]);
        if (lane == 0) pout[sid_sm[si]] = es / ssum;
    }
}

// ---------------- unified levels kernel (R5 macro-structure): one group per block ------
__global__ __launch_bounds__(128)
void levels_kernel(const float* __restrict__ x,
                   const int* __restrict__ labels,
                   const float* __restrict__ W)
{
    __shared__ float4 xsv[8 * 128];        // 16 KB
    __shared__ float  part[4 * 8 * 32];    // 4 KB
    __shared__ int    sid_sm[8];
    __shared__ int    step_sm[8];

    const int blk = blockIdx.x;

    if (blk < L0_BLOCKS) {
        process_group_scalar<8>(x, labels, W, d_p[0], xsv, part, sid_sm, step_sm,
                                /*node=*/0, /*shift=*/10, blk * 8, 8, false);
    } else if (blk < L0_BLOCKS + L1_SLOTS) {
        const int i = blk - L0_BLOCKS;
        if (i >= d_g1off[32]) return;
        const int g    = find_bucket(d_g1off, 32, i);
        const int base = d_start[g * 32] + (i - d_g1off[g]) * 8;
        const int S    = min(8, d_start[g * 32 + 32] - base);
        process_group_scalar<8>(x, labels, W, d_p[1], xsv, part, sid_sm, step_sm,
                                1 + g, /*shift=*/5, base, S, true);
    } else {
        const int i = blk - (L0_BLOCKS + L1_SLOTS);
        if (i >= d_g2off[NBKT]) return;
        const int k    = find_bucket(d_g2off, NBKT, i);
        const int base = d_start[k] + (i - d_g2off[k]) * 4;
        const int S    = min(4, d_start[k + 1] - base);
        process_group_vec4(x, labels, W, d_p[2], xsv, part, sid_sm, step_sm,
                           33 + k, base, S);
    }
}

__global__ __launch_bounds__(256)
void combine_kernel(float* __restrict__ out)
{
    const int b = blockIdx.x * 256 + threadIdx.x;
    out[b] = d_p[0][b] * d_p[1][b] * d_p[2][b];
}

extern "C" void kernel_launch(void* const* d_in, const int* in_sizes, int n_in,
                              void* d_out, int out_size)
{
    const float* x      = (const float*)d_in[0];   // [4096, 512] f32
    const int*   labels = (const int*)d_in[1];     // [4096] i32
    const float* W      = (const float*)d_in[2];   // [1057, 512, 32] f32
    float*       out    = (float*)d_out;           // [4096] f32

    tables_kernel <<<1, 1024>>>(labels);
    scatter_kernel<<<16, 256>>>(labels);
    levels_kernel <<<L0_BLOCKS + L1_SLOTS + L2_SLOTS, 128>>>(x, labels, W);
    combine_kernel<<<BATCH / 256, 256>>>(out);
}